// round 1
// baseline (speedup 1.0000x reference)
#include <cuda_runtime.h>
#include <math.h>

#define BB 512
#define TT 256
#define EE 256
#define UU 512
#define G4 2048   // 4*U
#define VV 10000
#define HH 64

// ---- scratch (static device memory; no allocations allowed) ----
__device__ float g_xw[2ull * BB * TT * G4];  // precomputed x@Wx, per direction (2 GB)
__device__ float g_h[2 * BB * UU];           // hidden state, fw/bw
__device__ float g_c[2 * BB * UU];           // cell state, fw/bw
__device__ float g_gates[2 * BB * G4];       // per-step gate pre-activations
__device__ float g_hidden[BB * HH];          // MLP hidden layer

__device__ __forceinline__ float sigf(float x) { return 1.0f / (1.0f + expf(-x)); }

// ---------------------------------------------------------------
// zero-init h and c (must happen every call: deterministic output)
// ---------------------------------------------------------------
__global__ void k_zero() {
    int i = blockIdx.x * blockDim.x + threadIdx.x;
    if (i < 2 * BB * UU) { g_h[i] = 0.0f; g_c[i] = 0.0f; }
}

// ---------------------------------------------------------------
// Precompute XW[dir][m, n] = sum_k emb[sent[m], k] * Wx[k, n]
// M = B*T = 131072, N = 2048, K = E = 256.
// 128x128 tile, Ktile=8, 256 threads, 8x8 microtile.
// Embedding gather fused into A-tile load.
// ---------------------------------------------------------------
__global__ __launch_bounds__(256) void k_pre(const int* __restrict__ sent,
                                             const float* __restrict__ emb,
                                             const float* __restrict__ WxF,
                                             const float* __restrict__ WxB) {
    const int dir = blockIdx.z;
    const float* __restrict__ Wx = dir ? WxB : WxF;
    const int n0 = blockIdx.x * 128;
    const size_t m0 = (size_t)blockIdx.y * 128;

    __shared__ float As[8][128];
    __shared__ float Bs[8][128];
    __shared__ int tok[128];

    const int tid = threadIdx.x;
    if (tid < 128) tok[tid] = sent[m0 + tid];
    __syncthreads();

    const int ty = tid >> 4;          // 0..15
    const int tx = tid & 15;          // 0..15
    const int ar = tid >> 1;          // 0..127 (A row within tile)
    const int ak = (tid & 1) * 4;     // 0 or 4 (A k-offset)
    const int br = tid >> 5;          // 0..7   (B k-row)
    const int bc = (tid & 31) * 4;    // 0..124 (B col)

    float acc[8][8];
#pragma unroll
    for (int i = 0; i < 8; i++)
#pragma unroll
        for (int j = 0; j < 8; j++) acc[i][j] = 0.0f;

    const int arow_tok = tok[ar];

    for (int kk = 0; kk < EE; kk += 8) {
        float4 av = *(const float4*)(emb + (size_t)arow_tok * EE + kk + ak);
        As[ak + 0][ar] = av.x; As[ak + 1][ar] = av.y;
        As[ak + 2][ar] = av.z; As[ak + 3][ar] = av.w;
        float4 bv = *(const float4*)(Wx + (size_t)(kk + br) * G4 + n0 + bc);
        *(float4*)&Bs[br][bc] = bv;
        __syncthreads();
#pragma unroll
        for (int k = 0; k < 8; k++) {
            float a[8], b[8];
            *(float4*)(a)     = *(const float4*)&As[k][ty * 8];
            *(float4*)(a + 4) = *(const float4*)&As[k][ty * 8 + 4];
            *(float4*)(b)     = *(const float4*)&Bs[k][tx * 8];
            *(float4*)(b + 4) = *(const float4*)&Bs[k][tx * 8 + 4];
#pragma unroll
            for (int i = 0; i < 8; i++)
#pragma unroll
                for (int j = 0; j < 8; j++) acc[i][j] = fmaf(a[i], b[j], acc[i][j]);
        }
        __syncthreads();
    }

    float* out = g_xw + (size_t)dir * BB * TT * G4;
#pragma unroll
    for (int i = 0; i < 8; i++) {
        size_t row = m0 + (size_t)ty * 8 + i;
        float4* o = (float4*)(out + row * G4 + n0 + tx * 8);
        o[0] = make_float4(acc[i][0], acc[i][1], acc[i][2], acc[i][3]);
        o[1] = make_float4(acc[i][4], acc[i][5], acc[i][6], acc[i][7]);
    }
}

// ---------------------------------------------------------------
// One recurrence step: gates[dir][b,n] = h[dir] @ Wh[dir] + XW[dir][b,time,n] + bias[n]
// M = 512, N = 2048, K = 512. blockIdx.z = direction.
// ---------------------------------------------------------------
__global__ __launch_bounds__(256) void k_step(const float* __restrict__ WhF,
                                              const float* __restrict__ WhB,
                                              const float* __restrict__ bF,
                                              const float* __restrict__ bB, int t) {
    const int dir = blockIdx.z;
    const float* __restrict__ Wh = dir ? WhB : WhF;
    const float* __restrict__ bias = dir ? bB : bF;
    const int time = dir ? (TT - 1 - t) : t;
    const float* __restrict__ A = g_h + (size_t)dir * BB * UU;
    const int n0 = blockIdx.x * 128;
    const int m0 = blockIdx.y * 128;

    __shared__ float As[8][128];
    __shared__ float Bs[8][128];

    const int tid = threadIdx.x;
    const int ty = tid >> 4, tx = tid & 15;
    const int ar = tid >> 1, ak = (tid & 1) * 4;
    const int br = tid >> 5, bc = (tid & 31) * 4;

    float acc[8][8];
#pragma unroll
    for (int i = 0; i < 8; i++)
#pragma unroll
        for (int j = 0; j < 8; j++) acc[i][j] = 0.0f;

    for (int kk = 0; kk < UU; kk += 8) {
        float4 av = *(const float4*)(A + (size_t)(m0 + ar) * UU + kk + ak);
        As[ak + 0][ar] = av.x; As[ak + 1][ar] = av.y;
        As[ak + 2][ar] = av.z; As[ak + 3][ar] = av.w;
        float4 bv = *(const float4*)(Wh + (size_t)(kk + br) * G4 + n0 + bc);
        *(float4*)&Bs[br][bc] = bv;
        __syncthreads();
#pragma unroll
        for (int k = 0; k < 8; k++) {
            float a[8], b[8];
            *(float4*)(a)     = *(const float4*)&As[k][ty * 8];
            *(float4*)(a + 4) = *(const float4*)&As[k][ty * 8 + 4];
            *(float4*)(b)     = *(const float4*)&Bs[k][tx * 8];
            *(float4*)(b + 4) = *(const float4*)&Bs[k][tx * 8 + 4];
#pragma unroll
            for (int i = 0; i < 8; i++)
#pragma unroll
                for (int j = 0; j < 8; j++) acc[i][j] = fmaf(a[i], b[j], acc[i][j]);
        }
        __syncthreads();
    }

    const size_t xwbase = (size_t)dir * BB * TT * G4;
#pragma unroll
    for (int i = 0; i < 8; i++) {
        const int b = m0 + ty * 8 + i;
        const float* xw = g_xw + xwbase + ((size_t)b * TT + time) * G4 + n0 + tx * 8;
        float* gr = g_gates + ((size_t)dir * BB + b) * G4 + n0 + tx * 8;
        const float* bs = bias + n0 + tx * 8;
#pragma unroll
        for (int j = 0; j < 8; j++) gr[j] = acc[i][j] + xw[j] + bs[j];
    }
}

// ---------------------------------------------------------------
// LSTM cell elementwise update (both directions)
// ---------------------------------------------------------------
__global__ void k_cell() {
    int i = blockIdx.x * blockDim.x + threadIdx.x;
    if (i >= 2 * BB * UU) return;
    int dir = i / (BB * UU);
    int r = i % (BB * UU);
    int b = r / UU;
    int u = r % UU;
    const float* gt = g_gates + ((size_t)dir * BB + b) * G4;
    float ig = sigf(gt[u]);
    float fg = sigf(gt[UU + u]);
    float gg = tanhf(gt[2 * UU + u]);
    float og = sigf(gt[3 * UU + u]);
    float c = fg * g_c[i] + ig * gg;
    g_c[i] = c;
    g_h[i] = og * tanhf(c);
}

// ---------------------------------------------------------------
// hidden = relu(concat(h_fw, h_bw) @ W1 + b1); one CTA per batch row
// ---------------------------------------------------------------
__global__ void k_hidden(const float* __restrict__ W1, const float* __restrict__ b1) {
    int b = blockIdx.x;
    int j = threadIdx.x;  // 64 threads
    __shared__ float hrow[2 * UU];
    for (int k = j; k < UU; k += HH) {
        hrow[k] = g_h[(size_t)b * UU + k];
        hrow[UU + k] = g_h[(size_t)BB * UU + (size_t)b * UU + k];
    }
    __syncthreads();
    float s = b1[j];
    for (int k = 0; k < 2 * UU; k++) s = fmaf(hrow[k], W1[(size_t)k * HH + j], s);
    g_hidden[b * HH + j] = fmaxf(s, 0.0f);
}

// ---------------------------------------------------------------
// out[b, :] = softmax(hidden[b] @ W2 + b2); one CTA (256 thr) per row
// ---------------------------------------------------------------
__global__ void k_out(const float* __restrict__ W2, const float* __restrict__ b2,
                      float* __restrict__ out) {
    int b = blockIdx.x;
    int tid = threadIdx.x;
    __shared__ float hid[HH];
    __shared__ float red[256];
    if (tid < HH) hid[tid] = g_hidden[b * HH + tid];
    __syncthreads();

    float lmax = -3.0e38f;
    for (int v = tid; v < VV; v += 256) {
        float s = b2[v];
#pragma unroll
        for (int k = 0; k < HH; k++) s = fmaf(hid[k], W2[(size_t)k * VV + v], s);
        out[(size_t)b * VV + v] = s;
        lmax = fmaxf(lmax, s);
    }
    red[tid] = lmax;
    __syncthreads();
    for (int s = 128; s > 0; s >>= 1) {
        if (tid < s) red[tid] = fmaxf(red[tid], red[tid + s]);
        __syncthreads();
    }
    float mx = red[0];
    __syncthreads();

    float lsum = 0.0f;
    for (int v = tid; v < VV; v += 256) {
        float e = expf(out[(size_t)b * VV + v] - mx);
        out[(size_t)b * VV + v] = e;
        lsum += e;
    }
    red[tid] = lsum;
    __syncthreads();
    for (int s = 128; s > 0; s >>= 1) {
        if (tid < s) red[tid] += red[tid + s];
        __syncthreads();
    }
    float inv = 1.0f / red[0];
    __syncthreads();

    for (int v = tid; v < VV; v += 256) out[(size_t)b * VV + v] *= inv;
}

// ---------------------------------------------------------------
extern "C" void kernel_launch(void* const* d_in, const int* in_sizes, int n_in,
                              void* d_out, int out_size) {
    const int*   sent = (const int*)d_in[0];
    const float* emb  = (const float*)d_in[1];
    const float* WxF  = (const float*)d_in[2];
    const float* WhF  = (const float*)d_in[3];
    const float* bF   = (const float*)d_in[4];
    const float* WxB  = (const float*)d_in[5];
    const float* WhB  = (const float*)d_in[6];
    const float* bB   = (const float*)d_in[7];
    const float* W1   = (const float*)d_in[8];
    const float* b1   = (const float*)d_in[9];
    const float* W2   = (const float*)d_in[10];
    const float* b2   = (const float*)d_in[11];
    float* out = (float*)d_out;

    k_zero<<<(2 * BB * UU + 255) / 256, 256>>>();

    dim3 gp(G4 / 128, (BB * TT) / 128, 2);  // (16, 1024, 2)
    k_pre<<<gp, 256>>>(sent, emb, WxF, WxB);

    dim3 gs(G4 / 128, BB / 128, 2);  // (16, 4, 2)
    for (int t = 0; t < TT; t++) {
        k_step<<<gs, 256>>>(WhF, WhB, bF, bB, t);
        k_cell<<<(2 * BB * UU + 255) / 256, 256>>>();
    }

    k_hidden<<<BB, HH>>>(W1, b1);
    k_out<<<BB, 256>>>(W2, b2, out);
}

// round 3
// speedup vs baseline: 1.8831x; 1.8831x over previous
#include <cuda_runtime.h>
#include <cuda_bf16.h>
#include <math.h>

#define BB 512
#define TT 256
#define EE 256
#define UU 512
#define G4 2048   // 4*U
#define VV 10000
#define HH 64

// ---- scratch (static device memory) ----
__device__ float g_xw[2ull * BB * TT * G4];  // precomputed x@Wx (gate-interleaved cols)
__device__ float g_h[2 * BB * UU];
__device__ float g_c[2 * BB * UU];
__device__ float g_hidden[BB * HH];
__device__ float g_wx[2 * EE * G4];          // interleaved Wx
__device__ float g_wh[2 * UU * G4];          // interleaved Wh
__device__ float g_b[2 * G4];                // interleaved bias

__device__ __forceinline__ float sigf(float x) { return 1.0f / (1.0f + expf(-x)); }

// split (x0,x1) into hi/lo bf16x2 packed registers; x0 in low half (k-first)
__device__ __forceinline__ void splitpk(float x0, float x1, unsigned& hi, unsigned& lo) {
    __nv_bfloat162 h = __floats2bfloat162_rn(x0, x1);
    float r0 = x0 - __bfloat162float(h.x);
    float r1 = x1 - __bfloat162float(h.y);
    __nv_bfloat162 l = __floats2bfloat162_rn(r0, r1);
    hi = *reinterpret_cast<unsigned*>(&h);
    lo = *reinterpret_cast<unsigned*>(&l);
}

__device__ __forceinline__ void mma_bf16(float c[4], const unsigned a[4], const unsigned b[2]) {
    asm volatile(
        "mma.sync.aligned.m16n8k16.row.col.f32.bf16.bf16.f32 "
        "{%0,%1,%2,%3}, {%4,%5,%6,%7}, {%8,%9}, {%0,%1,%2,%3};"
        : "+f"(c[0]), "+f"(c[1]), "+f"(c[2]), "+f"(c[3])
        : "r"(a[0]), "r"(a[1]), "r"(a[2]), "r"(a[3]), "r"(b[0]), "r"(b[1]));
}

// ---------------------------------------------------------------
__global__ void k_zero() {
    int i = blockIdx.x * blockDim.x + threadIdx.x;
    if (i < 2 * BB * UU) { g_h[i] = 0.0f; g_c[i] = 0.0f; }
}

// ---------------------------------------------------------------
// gate-interleave weights: j = 4u+g, orig col = g*U+u
// ---------------------------------------------------------------
__global__ void k_prep(const float* __restrict__ WxF, const float* __restrict__ WhF,
                       const float* __restrict__ bF,  const float* __restrict__ WxB,
                       const float* __restrict__ WhB, const float* __restrict__ bB) {
    const int PER = (EE + UU + 1) * G4;
    int tid = blockIdx.x * 256 + threadIdx.x;
    if (tid >= 2 * PER) return;
    int dir = tid / PER;
    int r = tid % PER;
    int row = r / G4;
    int j = r % G4;
    int gsel = j & 3, u = j >> 2;
    int oc = gsel * UU + u;
    const float* Wx = dir ? WxB : WxF;
    const float* Wh = dir ? WhB : WhF;
    const float* bs = dir ? bB : bF;
    if (row < EE) {
        g_wx[(size_t)dir * EE * G4 + (size_t)row * G4 + j] = Wx[(size_t)row * G4 + oc];
    } else if (row < EE + UU) {
        int k = row - EE;
        g_wh[(size_t)dir * UU * G4 + (size_t)k * G4 + j] = Wh[(size_t)k * G4 + oc];
    } else {
        g_b[dir * G4 + j] = bs[oc];
    }
}

// ---------------------------------------------------------------
// Precompute XW = gather(emb, sent) @ Wx_int  (bf16 split-3 mma)
// M = 131072, N = 2048, K = 256. Tile 128x128, KC=16, 256 thr.
// Warps 2m x 4n; warp tile 64x32 (mt=4, nt=4).
// ---------------------------------------------------------------
__global__ __launch_bounds__(256) void k_pre(const int* __restrict__ sent,
                                             const float* __restrict__ emb) {
    const int dir = blockIdx.z;
    const float* __restrict__ Wx = g_wx + (size_t)dir * EE * G4;
    const int n0 = blockIdx.x * 128;
    const size_t m0 = (size_t)blockIdx.y * 128;

    __shared__ unsigned Ah[2][8][136], Al[2][8][136];
    __shared__ unsigned Bh[2][8][136], Bl[2][8][136];
    __shared__ int tok[128];

    const int tid = threadIdx.x;
    const int lane = tid & 31, w = tid >> 5;
    const int wm = w & 1, wn = w >> 1;
    const int gi = lane >> 2, ct = lane & 3;

    if (tid < 128) tok[tid] = sent[m0 + tid];
    __syncthreads();

    const int rowA = tid >> 1, kA = (tid & 1) * 8, kpA = (tid & 1) * 4;
    const int kpB = tid >> 5, colB = (tid & 31) * 4;
    const int tokA = tok[rowA];

    float acc[4][4][4];
#pragma unroll
    for (int i = 0; i < 4; i++)
#pragma unroll
        for (int j = 0; j < 4; j++)
#pragma unroll
            for (int q = 0; q < 4; q++) acc[i][j][q] = 0.0f;

    const int NK = EE / 16;
    float4 a0, a1, b0, b1;
    {
        const float* pa = emb + (size_t)tokA * EE + kA;
        a0 = *(const float4*)pa; a1 = *(const float4*)(pa + 4);
        const float* pb = Wx + (size_t)(2 * kpB) * G4 + n0 + colB;
        b0 = *(const float4*)pb; b1 = *(const float4*)(pb + G4);
    }
    {
        float ae[8] = {a0.x, a0.y, a0.z, a0.w, a1.x, a1.y, a1.z, a1.w};
#pragma unroll
        for (int p = 0; p < 4; p++)
            splitpk(ae[2 * p], ae[2 * p + 1], Ah[0][kpA + p][rowA], Al[0][kpA + p][rowA]);
        float be0[4] = {b0.x, b0.y, b0.z, b0.w};
        float be1[4] = {b1.x, b1.y, b1.z, b1.w};
#pragma unroll
        for (int c = 0; c < 4; c++)
            splitpk(be0[c], be1[c], Bh[0][kpB][colB + c], Bl[0][kpB][colB + c]);
    }
    __syncthreads();

    int cur = 0;
    for (int kk = 1; kk <= NK; kk++) {
        float4 na0, na1, nb0, nb1;
        if (kk < NK) {
            const float* pa = emb + (size_t)tokA * EE + kk * 16 + kA;
            na0 = *(const float4*)pa; na1 = *(const float4*)(pa + 4);
            const float* pb = Wx + (size_t)(kk * 16 + 2 * kpB) * G4 + n0 + colB;
            nb0 = *(const float4*)pb; nb1 = *(const float4*)(pb + G4);
        }
        unsigned afh[4][4], afl[4][4], bfh[4][2], bfl[4][2];
#pragma unroll
        for (int mt = 0; mt < 4; mt++) {
            int r = wm * 64 + mt * 16 + gi;
            afh[mt][0] = Ah[cur][ct][r];     afh[mt][1] = Ah[cur][ct][r + 8];
            afh[mt][2] = Ah[cur][ct + 4][r]; afh[mt][3] = Ah[cur][ct + 4][r + 8];
            afl[mt][0] = Al[cur][ct][r];     afl[mt][1] = Al[cur][ct][r + 8];
            afl[mt][2] = Al[cur][ct + 4][r]; afl[mt][3] = Al[cur][ct + 4][r + 8];
        }
#pragma unroll
        for (int nt = 0; nt < 4; nt++) {
            int cl = wn * 32 + nt * 8 + gi;
            bfh[nt][0] = Bh[cur][ct][cl]; bfh[nt][1] = Bh[cur][ct + 4][cl];
            bfl[nt][0] = Bl[cur][ct][cl]; bfl[nt][1] = Bl[cur][ct + 4][cl];
        }
#pragma unroll
        for (int mt = 0; mt < 4; mt++)
#pragma unroll
            for (int nt = 0; nt < 4; nt++) {
                mma_bf16(acc[mt][nt], afh[mt], bfh[nt]);
                mma_bf16(acc[mt][nt], afh[mt], bfl[nt]);
                mma_bf16(acc[mt][nt], afl[mt], bfh[nt]);
            }
        if (kk < NK) {
            int nx = cur ^ 1;
            float ae[8] = {na0.x, na0.y, na0.z, na0.w, na1.x, na1.y, na1.z, na1.w};
#pragma unroll
            for (int p = 0; p < 4; p++)
                splitpk(ae[2 * p], ae[2 * p + 1], Ah[nx][kpA + p][rowA], Al[nx][kpA + p][rowA]);
            float be0[4] = {nb0.x, nb0.y, nb0.z, nb0.w};
            float be1[4] = {nb1.x, nb1.y, nb1.z, nb1.w};
#pragma unroll
            for (int c = 0; c < 4; c++)
                splitpk(be0[c], be1[c], Bh[nx][kpB][colB + c], Bl[nx][kpB][colB + c]);
            __syncthreads();
        }
        cur ^= 1;
    }

    float* out = g_xw + (size_t)dir * BB * TT * G4;
#pragma unroll
    for (int mt = 0; mt < 4; mt++) {
#pragma unroll
        for (int nt = 0; nt < 4; nt++) {
            size_t r0 = m0 + wm * 64 + mt * 16 + gi;
            int cl = n0 + wn * 32 + nt * 8 + 2 * ct;
            *(float2*)(out + r0 * G4 + cl) = make_float2(acc[mt][nt][0], acc[mt][nt][1]);
            *(float2*)(out + (r0 + 8) * G4 + cl) = make_float2(acc[mt][nt][2], acc[mt][nt][3]);
        }
    }
}

// ---------------------------------------------------------------
// Scan step: gates = h @ Wh_int + xw[:,time,:] + b_int, fused LSTM cell.
// M = 512, N = 2048, K = 512. Tile 128x64, KC=16, 256 thr.
// Warps 4m x 2n; warp tile 32x32 (mt=2, nt=4).
// ---------------------------------------------------------------
__global__ __launch_bounds__(256) void k_scan(int t) {
    const int dir = blockIdx.z;
    const float* __restrict__ Wh = g_wh + (size_t)dir * UU * G4;
    const float* __restrict__ bias = g_b + dir * G4;
    const int time = dir ? (TT - 1 - t) : t;
    const float* __restrict__ A = g_h + (size_t)dir * BB * UU;
    const int n0 = blockIdx.x * 64;
    const int m0 = blockIdx.y * 128;

    __shared__ unsigned Ah[2][8][136], Al[2][8][136];
    __shared__ unsigned Bh[2][8][72], Bl[2][8][72];

    const int tid = threadIdx.x;
    const int lane = tid & 31, w = tid >> 5;
    const int wm = w & 3, wn = w >> 2;
    const int gi = lane >> 2, ct = lane & 3;

    const int rowA = tid >> 1, kA = (tid & 1) * 8, kpA = (tid & 1) * 4;
    const int kpB = tid >> 5, c2 = (tid & 31) * 2;

    float acc[2][4][4];
#pragma unroll
    for (int i = 0; i < 2; i++)
#pragma unroll
        for (int j = 0; j < 4; j++)
#pragma unroll
            for (int q = 0; q < 4; q++) acc[i][j][q] = 0.0f;

    const int NK = UU / 16;
    {
        const float* pa = A + (size_t)(m0 + rowA) * UU + kA;
        float4 a0 = *(const float4*)pa, a1 = *(const float4*)(pa + 4);
        const float* pb = Wh + (size_t)(2 * kpB) * G4 + n0 + c2;
        float2 b0 = *(const float2*)pb, b1 = *(const float2*)(pb + G4);
        float ae[8] = {a0.x, a0.y, a0.z, a0.w, a1.x, a1.y, a1.z, a1.w};
#pragma unroll
        for (int p = 0; p < 4; p++)
            splitpk(ae[2 * p], ae[2 * p + 1], Ah[0][kpA + p][rowA], Al[0][kpA + p][rowA]);
        splitpk(b0.x, b1.x, Bh[0][kpB][c2], Bl[0][kpB][c2]);
        splitpk(b0.y, b1.y, Bh[0][kpB][c2 + 1], Bl[0][kpB][c2 + 1]);
    }
    __syncthreads();

    int cur = 0;
    for (int kk = 1; kk <= NK; kk++) {
        float4 na0, na1; float2 nb0, nb1;
        if (kk < NK) {
            const float* pa = A + (size_t)(m0 + rowA) * UU + kk * 16 + kA;
            na0 = *(const float4*)pa; na1 = *(const float4*)(pa + 4);
            const float* pb = Wh + (size_t)(kk * 16 + 2 * kpB) * G4 + n0 + c2;
            nb0 = *(const float2*)pb; nb1 = *(const float2*)(pb + G4);
        }
        unsigned afh[2][4], afl[2][4], bfh[4][2], bfl[4][2];
#pragma unroll
        for (int mt = 0; mt < 2; mt++) {
            int r = wm * 32 + mt * 16 + gi;
            afh[mt][0] = Ah[cur][ct][r];     afh[mt][1] = Ah[cur][ct][r + 8];
            afh[mt][2] = Ah[cur][ct + 4][r]; afh[mt][3] = Ah[cur][ct + 4][r + 8];
            afl[mt][0] = Al[cur][ct][r];     afl[mt][1] = Al[cur][ct][r + 8];
            afl[mt][2] = Al[cur][ct + 4][r]; afl[mt][3] = Al[cur][ct + 4][r + 8];
        }
#pragma unroll
        for (int nt = 0; nt < 4; nt++) {
            int cl = wn * 32 + nt * 8 + gi;
            bfh[nt][0] = Bh[cur][ct][cl]; bfh[nt][1] = Bh[cur][ct + 4][cl];
            bfl[nt][0] = Bl[cur][ct][cl]; bfl[nt][1] = Bl[cur][ct + 4][cl];
        }
#pragma unroll
        for (int mt = 0; mt < 2; mt++)
#pragma unroll
            for (int nt = 0; nt < 4; nt++) {
                mma_bf16(acc[mt][nt], afh[mt], bfh[nt]);
                mma_bf16(acc[mt][nt], afh[mt], bfl[nt]);
                mma_bf16(acc[mt][nt], afl[mt], bfh[nt]);
            }
        if (kk < NK) {
            int nx = cur ^ 1;
            float ae[8] = {na0.x, na0.y, na0.z, na0.w, na1.x, na1.y, na1.z, na1.w};
#pragma unroll
            for (int p = 0; p < 4; p++)
                splitpk(ae[2 * p], ae[2 * p + 1], Ah[nx][kpA + p][rowA], Al[nx][kpA + p][rowA]);
            splitpk(nb0.x, nb1.x, Bh[nx][kpB][c2], Bl[nx][kpB][c2]);
            splitpk(nb0.y, nb1.y, Bh[nx][kpB][c2 + 1], Bl[nx][kpB][c2 + 1]);
            __syncthreads();
        }
        cur ^= 1;
    }

    // Fused epilogue: add xw + bias, shfl-pair gates, LSTM cell update.
    const size_t hbase = (size_t)dir * BB * UU;
    const size_t xwdir = (size_t)dir * BB * TT;
#pragma unroll
    for (int mt = 0; mt < 2; mt++) {
#pragma unroll
        for (int nt = 0; nt < 4; nt++) {
            int r0 = m0 + wm * 32 + mt * 16 + gi;
            int r1 = r0 + 8;
            int cl = n0 + wn * 32 + nt * 8 + 2 * ct;
            float2 x0 = *(const float2*)(g_xw + (xwdir + (size_t)r0 * TT + time) * G4 + cl);
            float2 x1 = *(const float2*)(g_xw + (xwdir + (size_t)r1 * TT + time) * G4 + cl);
            float2 bb = *(const float2*)(bias + cl);
            float p00 = acc[mt][nt][0] + x0.x + bb.x;
            float p01 = acc[mt][nt][1] + x0.y + bb.y;
            float p10 = acc[mt][nt][2] + x1.x + bb.x;
            float p11 = acc[mt][nt][3] + x1.y + bb.y;
            float q00 = __shfl_xor_sync(0xFFFFFFFFu, p00, 1);
            float q01 = __shfl_xor_sync(0xFFFFFFFFu, p01, 1);
            float q10 = __shfl_xor_sync(0xFFFFFFFFu, p10, 1);
            float q11 = __shfl_xor_sync(0xFFFFFFFFu, p11, 1);
            if ((ct & 1) == 0) {
                int u = cl >> 2;
                size_t i0 = hbase + (size_t)r0 * UU + u;
                size_t i1 = hbase + (size_t)r1 * UU + u;
                float c0 = sigf(p01) * g_c[i0] + sigf(p00) * tanhf(q00);
                g_c[i0] = c0;
                g_h[i0] = sigf(q01) * tanhf(c0);
                float c1 = sigf(p11) * g_c[i1] + sigf(p10) * tanhf(q10);
                g_c[i1] = c1;
                g_h[i1] = sigf(q11) * tanhf(c1);
            }
        }
    }
}

// ---------------------------------------------------------------
__global__ void k_hidden(const float* __restrict__ W1, const float* __restrict__ b1) {
    int b = blockIdx.x;
    int j = threadIdx.x;  // 64
    __shared__ float hrow[2 * UU];
    for (int k = j; k < UU; k += HH) {
        hrow[k] = g_h[(size_t)b * UU + k];
        hrow[UU + k] = g_h[(size_t)BB * UU + (size_t)b * UU + k];
    }
    __syncthreads();
    float s = b1[j];
    for (int k = 0; k < 2 * UU; k++) s = fmaf(hrow[k], W1[(size_t)k * HH + j], s);
    g_hidden[b * HH + j] = fmaxf(s, 0.0f);
}

// ---------------------------------------------------------------
__global__ void k_out(const float* __restrict__ W2, const float* __restrict__ b2,
                      float* __restrict__ out) {
    int b = blockIdx.x;
    int tid = threadIdx.x;
    __shared__ float hid[HH];
    __shared__ float red[256];
    if (tid < HH) hid[tid] = g_hidden[b * HH + tid];
    __syncthreads();

    float lmax = -3.0e38f;
    for (int v = tid; v < VV; v += 256) {
        float s = b2[v];
#pragma unroll
        for (int k = 0; k < HH; k++) s = fmaf(hid[k], W2[(size_t)k * VV + v], s);
        out[(size_t)b * VV + v] = s;
        lmax = fmaxf(lmax, s);
    }
    red[tid] = lmax;
    __syncthreads();
    for (int s = 128; s > 0; s >>= 1) {
        if (tid < s) red[tid] = fmaxf(red[tid], red[tid + s]);
        __syncthreads();
    }
    float mx = red[0];
    __syncthreads();

    float lsum = 0.0f;
    for (int v = tid; v < VV; v += 256) {
        float e = expf(out[(size_t)b * VV + v] - mx);
        out[(size_t)b * VV + v] = e;
        lsum += e;
    }
    red[tid] = lsum;
    __syncthreads();
    for (int s = 128; s > 0; s >>= 1) {
        if (tid < s) red[tid] += red[tid + s];
        __syncthreads();
    }
    float inv = 1.0f / red[0];
    __syncthreads();

    for (int v = tid; v < VV; v += 256) out[(size_t)b * VV + v] *= inv;
}

// ---------------------------------------------------------------
extern "C" void kernel_launch(void* const* d_in, const int* in_sizes, int n_in,
                              void* d_out, int out_size) {
    const int*   sent = (const int*)d_in[0];
    const float* emb  = (const float*)d_in[1];
    const float* WxF  = (const float*)d_in[2];
    const float* WhF  = (const float*)d_in[3];
    const float* bF   = (const float*)d_in[4];
    const float* WxB  = (const float*)d_in[5];
    const float* WhB  = (const float*)d_in[6];
    const float* bB   = (const float*)d_in[7];
    const float* W1   = (const float*)d_in[8];
    const float* b1   = (const float*)d_in[9];
    const float* W2   = (const float*)d_in[10];
    const float* b2   = (const float*)d_in[11];
    float* out = (float*)d_out;

    k_zero<<<(2 * BB * UU + 255) / 256, 256>>>();

    const int prep_total = 2 * (EE + UU + 1) * G4;
    k_prep<<<(prep_total + 255) / 256, 256>>>(WxF, WhF, bF, WxB, WhB, bB);

    dim3 gp(G4 / 128, (BB * TT) / 128, 2);  // (16, 1024, 2)
    k_pre<<<gp, 256>>>(sent, emb);

    dim3 gs(G4 / 64, BB / 128, 2);  // (32, 4, 2)
    for (int t = 0; t < TT; t++) {
        k_scan<<<gs, 256>>>(t);
    }

    k_hidden<<<BB, HH>>>(W1, b1);
    k_out<<<BB, 256>>>(W2, b2, out);
}